// round 11
// baseline (speedup 1.0000x reference)
#include <cuda_runtime.h>
#include <cuda_fp16.h>
#include <math.h>
#include <stdint.h>

// ---------------------------------------------------------------------------
// MiniGRUConv2d4 on GB300 (compute_103 PTX target -> legacy mma.sync path):
//   pass 1: transpose xs -> xh[b][y][x][ci] fp16
//   pass 2: 3x(conv3x3+BN[+sigmoid]) implicit GEMM, fp16 mma.sync.m16n8k16.
//           ONE CTA = 128 px x ALL 768 couts (loop of 6 m-blocks over a
//           resident B halo); A weights stream via continuous cp.async ring.
//   pass 3: vertical scans: segment compose + fused apply/horizontal tail.
// ---------------------------------------------------------------------------

#define B_  4
#define CIN 64
#define C4  256

static __device__ __half gH[(size_t)B_ * C4 * 256 * 256];            // h plane
static __device__ __half gZ[(size_t)B_ * C4 * 256 * 256];            // z plane
static __device__ __half gS[(size_t)B_ * C4 * 256 * 256];            // s plane
static __device__ __align__(16) __half gXh[(size_t)B_ * 256 * 256 * 64];
static __device__ __align__(16) __half gWtH[768 * 576];
static __device__ float gBias[768];
static __device__ float2 gSeg[2 * 4 * 64 * 8 * 256];                 // seg (A,B)

struct ConvParams {
    const float* w[3];
    const float* g[3];
    const float* b[3];
    const float* m[3];
    const float* v[3];
};

// ---------------- fast sigmoid (no MUFU) ------------------------------------
__device__ __forceinline__ float fast_sigmoid(float x)
{
    float u = -1.44269504f * x;
    u = fminf(fmaxf(u, -60.f), 60.f);
    float fi = rintf(u);
    float f  = u - fi;
    float p = 1.54035304e-4f;
    p = fmaf(p, f, 1.33335581e-3f);
    p = fmaf(p, f, 9.61812910e-3f);
    p = fmaf(p, f, 5.55041087e-2f);
    p = fmaf(p, f, 2.40226507e-1f);
    p = fmaf(p, f, 6.93147181e-1f);
    p = fmaf(p, f, 1.0f);
    int ei = (int)fi;
    float e = __int_as_float(__float_as_int(p) + (ei << 23));
    float d = 1.0f + e;
    float r = __int_as_float(0x7EF311C3 - __float_as_int(d));
    r = r * (2.0f - d * r);
    r = r * (2.0f - d * r);
    r = r * (2.0f - d * r);
    return r;
}

// ---------------- small helpers ---------------------------------------------
__device__ __forceinline__ uint32_t smem_u32(const void* p)
{
    uint32_t a;
    asm("{ .reg .u64 t; cvta.to.shared.u64 t, %1; cvt.u32.u64 %0, t; }"
        : "=r"(a) : "l"(p));
    return a;
}
__device__ __forceinline__ void cp16(uint32_t dst, const void* src)
{
    size_t g = __cvta_generic_to_global(src);
    asm volatile("cp.async.cg.shared.global [%0], [%1], 16;"
                 :: "r"(dst), "l"(g) : "memory");
}
__device__ __forceinline__ void sts_zero16(uint32_t a)
{
    asm volatile("st.shared.v4.u32 [%0], {%1,%1,%1,%1};" :: "r"(a), "r"(0u) : "memory");
}
__device__ __forceinline__ void ldsm_x4(uint32_t& r0, uint32_t& r1,
                                        uint32_t& r2, uint32_t& r3, uint32_t a)
{
    asm volatile("ldmatrix.sync.aligned.m8n8.x4.shared.b16 {%0,%1,%2,%3}, [%4];"
                 : "=r"(r0), "=r"(r1), "=r"(r2), "=r"(r3) : "r"(a));
}
// load 8 consecutive halves -> 8 floats
__device__ __forceinline__ void ld8h(const __half* p, float* d)
{
    uint4 u = *(const uint4*)p;
    const __half2* h = (const __half2*)&u;
    float2 f0 = __half22float2(h[0]);
    float2 f1 = __half22float2(h[1]);
    float2 f2 = __half22float2(h[2]);
    float2 f3 = __half22float2(h[3]);
    d[0] = f0.x; d[1] = f0.y; d[2] = f1.x; d[3] = f1.y;
    d[4] = f2.x; d[5] = f2.y; d[6] = f3.x; d[7] = f3.y;
}

// ---------------------------------------------------------------------------
// Prep: fold BN into fp16 weights, k = r*64+ci ordering; fp32 bias.
// ---------------------------------------------------------------------------
__global__ void prep_kernel(ConvParams P)
{
    int idx = blockIdx.x * 256 + threadIdx.x;
    if (idx < 768) {
        int set = idx >> 8, co = idx & 255;
        float inv = P.g[set][co] * rsqrtf(P.v[set][co] + 1e-5f);
        gBias[idx] = P.b[set][co] - P.m[set][co] * inv;
    }
    if (idx < 768 * 576) {
        int co_g = idx / 576;
        int k    = idx - co_g * 576;
        int r    = k >> 6;
        int ci   = k & 63;
        int set  = co_g >> 8;
        int co   = co_g & 255;
        float inv = P.g[set][co] * rsqrtf(P.v[set][co] + 1e-5f);
        gWtH[idx] = __float2half_rn(P.w[set][(co * 64 + ci) * 9 + r] * inv);
    }
}

// ---------------------------------------------------------------------------
// Transpose xs [b][ci][y][x] fp32 -> gXh [b][y][x][ci] fp16.
// ---------------------------------------------------------------------------
__global__ __launch_bounds__(256)
void xpose_kernel(const float* __restrict__ xs)
{
    __shared__ float S[64][129];
    const int xt = blockIdx.x;
    const int y  = blockIdx.y;
    const int b  = blockIdx.z;
    const int tid = threadIdx.x;

    const float* src = xs + (((size_t)b * CIN) << 16) + (y << 8) + xt * 128;
#pragma unroll
    for (int p = 0; p < 8; ++p) {
        int idx = tid + (p << 8);
        int ci  = idx >> 5;
        int x4  = idx & 31;
        float4 v = *(const float4*)(src + (((size_t)ci) << 16) + (x4 << 2));
        S[ci][x4 * 4 + 0] = v.x;
        S[ci][x4 * 4 + 1] = v.y;
        S[ci][x4 * 4 + 2] = v.z;
        S[ci][x4 * 4 + 3] = v.w;
    }
    __syncthreads();

    __half* dst = gXh + ((((size_t)b * 256 + y) * 256) + xt * 128) * 64;
#pragma unroll
    for (int p = 0; p < 4; ++p) {
        int chunk = tid + (p << 8);
        int g = chunk & 7;
        int x = chunk >> 3;
        int c0 = g * 8;
        __half2 h0 = __floats2half2_rn(S[c0 + 0][x], S[c0 + 1][x]);
        __half2 h1 = __floats2half2_rn(S[c0 + 2][x], S[c0 + 3][x]);
        __half2 h2 = __floats2half2_rn(S[c0 + 4][x], S[c0 + 5][x]);
        __half2 h3 = __floats2half2_rn(S[c0 + 6][x], S[c0 + 7][x]);
        uint4 val;
        val.x = *(uint32_t*)&h0; val.y = *(uint32_t*)&h1;
        val.z = *(uint32_t*)&h2; val.w = *(uint32_t*)&h3;
        *(uint4*)(dst + (size_t)x * 64 + g * 8) = val;
    }
}

// ---------------------------------------------------------------------------
// Conv: CTA = 128 px x 768 couts (6 m-blocks), 8 warps (4m x 2n) per block.
// B halo resident in smem; A ring streams 108 chunks of 128co x 32k.
// ---------------------------------------------------------------------------
#define BT_STRIDE 132
#define BT_BYTES  (3 * BT_STRIDE * 128)          // 50688
#define A_BUF     8192
#define SMEM_BYTES (BT_BYTES + 4 * A_BUF)        // 83456

__global__ __launch_bounds__(256, 2)
void conv_mma_kernel()
{
    extern __shared__ char smem[];
    const uint32_t sB = smem_u32(smem);
    const uint32_t sA = sB + BT_BYTES;

    const int tid = threadIdx.x;
    const int l   = tid & 31;
    const int w   = tid >> 5;
    const int wm  = w >> 1;            // 0..3 (32 co each)
    const int wn  = w & 1;             // 0..1 (64 px each)

    const int bx = blockIdx.x;         // 0..511
    const int y0 = bx >> 1;
    const int x0 = (bx & 1) << 7;
    const int b  = blockIdx.y;

    // ---- A ring producer: chunk s = (m_blk = s/18, kt = s%18) ----
    auto issueA = [&](int s) {
        if (s < 108) {
            int m_blk = s / 18;
            int kt    = s - m_blk * 18;
            uint32_t base = sA + (uint32_t)((s & 3) * A_BUF);
            const __half* src = gWtH + (size_t)(m_blk * 128) * 576 + kt * 32;
#pragma unroll
            for (int p = 0; p < 2; ++p) {
                int chunk = tid + (p << 8);
                int co  = chunk >> 2;
                int kpg = chunk & 3;
                uint32_t wrd = (uint32_t)(co << 4)
                             + (uint32_t)((kpg ^ ((co >> 1) & 3)) << 2);
                cp16(base + (wrd << 2), src + (size_t)co * 576 + (kpg << 3));
            }
        }
        asm volatile("cp.async.commit_group;" ::: "memory");
    };

    // ---- progressive B halo fill: row r goes in cp.async group r ----
    for (int row = 0; row < 3; ++row) {
        const int y = y0 - 1 + row;
        const bool rok = (unsigned)y < 256u;
        for (int t = tid; t < 1040; t += 256) {
            int slot = t >> 3;
            int g    = t & 7;
            int x    = x0 + slot - 1;
            uint32_t dst = sB + (uint32_t)(row * BT_STRIDE + slot) * 128
                         + (uint32_t)((g ^ (slot & 7)) << 4);
            if (rok && (unsigned)x < 256u)
                cp16(dst, gXh + ((((size_t)b * 256 + y) * 256 + x) * 64 + g * 8));
            else
                sts_zero16(dst);
        }
        issueA(row);
    }

    // ---- per-lane ldmatrix address constants ----
    const int hiA   = l >> 4;
    const int cA0   = (wm << 5) + (l & 15);
    const int cA1   = cA0 + 16;
    const int xa0   = (cA0 >> 1) & 3;
    const int xa1   = (cA1 >> 1) & 3;
    const uint32_t aoff0 = (uint32_t)(cA0 << 6);
    const uint32_t aoff1 = (uint32_t)(cA1 << 6);
    const int gsel  = (l >> 3) & 1;
    const int sbl   = (wn << 6) + (l & 7) + ((l >> 4) << 3);

    int step = 0;
    for (int m = 0; m < 6; ++m) {
        float acc[2][8][4];
#pragma unroll
        for (int mt = 0; mt < 2; ++mt)
#pragma unroll
            for (int nt = 0; nt < 8; ++nt)
#pragma unroll
                for (int c = 0; c < 4; ++c) acc[mt][nt][c] = 0.f;

        for (int kt = 0; kt < 18; ++kt) {
            asm volatile("cp.async.wait_group 2;" ::: "memory");
            __syncthreads();

            const uint32_t abuf = sA + (uint32_t)((step & 3) * A_BUF);
            const int r   = kt >> 1;
            const int row = r / 3;
            const int dxp = r - row * 3;
            const uint32_t rowbase = sB + (uint32_t)(row * BT_STRIDE) * 128;

#pragma unroll
            for (int ks = 0; ks < 2; ++ks) {
                const int kg = (ks << 1) + hiA;
                uint32_t a0[4], a1[4];
                ldsm_x4(a0[0], a0[1], a0[2], a0[3],
                        abuf + aoff0 + (uint32_t)((kg ^ xa0) << 4));
                ldsm_x4(a1[0], a1[1], a1[2], a1[3],
                        abuf + aoff1 + (uint32_t)((kg ^ xa1) << 4));

                const int ga = ((kt & 1) << 2) + (ks << 1) + gsel;
#pragma unroll
                for (int ntp = 0; ntp < 4; ++ntp) {
                    int slot = sbl + (ntp << 4) + dxp;
                    uint32_t addr = rowbase + (uint32_t)(slot << 7)
                                  + (uint32_t)((ga ^ (slot & 7)) << 4);
                    uint32_t b0, b1, b2, b3;
                    ldsm_x4(b0, b1, b2, b3, addr);

                    const int nt0 = ntp << 1;
#pragma unroll
                    for (int half = 0; half < 2; ++half) {
                        uint32_t bb0 = half ? b2 : b0;
                        uint32_t bb1 = half ? b3 : b1;
                        int nt = nt0 + half;
                        asm volatile(
                            "mma.sync.aligned.m16n8k16.row.col.f32.f16.f16.f32 "
                            "{%0,%1,%2,%3}, {%4,%5,%6,%7}, {%8,%9}, {%0,%1,%2,%3};"
                            : "+f"(acc[0][nt][0]), "+f"(acc[0][nt][1]),
                              "+f"(acc[0][nt][2]), "+f"(acc[0][nt][3])
                            : "r"(a0[0]), "r"(a0[1]), "r"(a0[2]), "r"(a0[3]),
                              "r"(bb0), "r"(bb1));
                        asm volatile(
                            "mma.sync.aligned.m16n8k16.row.col.f32.f16.f16.f32 "
                            "{%0,%1,%2,%3}, {%4,%5,%6,%7}, {%8,%9}, {%0,%1,%2,%3};"
                            : "+f"(acc[1][nt][0]), "+f"(acc[1][nt][1]),
                              "+f"(acc[1][nt][2]), "+f"(acc[1][nt][3])
                            : "r"(a1[0]), "r"(a1[1]), "r"(a1[2]), "r"(a1[3]),
                              "r"(bb0), "r"(bb1));
                    }
                }
            }
            issueA(step + 3);
            step++;
        }

        // ---- epilogue for m-block: bias; fp16 planes (+sigmoid on 0/2) ----
        const int m0v = m << 7;
        const int set = m0v >> 8;
        const int chb = m0v & 255;
#pragma unroll
        for (int mt = 0; mt < 2; ++mt) {
#pragma unroll
            for (int rr = 0; rr < 2; ++rr) {
                int cloc = (wm << 5) + (mt << 4) + (l >> 2) + (rr << 3);
                float bias = gBias[m0v + cloc];
                int ch = chb + cloc;
                size_t base = (((size_t)b * C4 + ch) << 16)
                            + ((size_t)y0 << 8) + x0;
#pragma unroll
                for (int nt = 0; nt < 8; ++nt) {
                    int n = (wn << 6) + (nt << 3) + ((l & 3) << 1);
                    float v0 = acc[mt][nt][rr * 2 + 0] + bias;
                    float v1 = acc[mt][nt][rr * 2 + 1] + bias;
                    if (set == 1) {
                        *(__half2*)&gH[base + n] = __floats2half2_rn(v0, v1);
                    } else {
                        __half2 h2 = __floats2half2_rn(fast_sigmoid(v0),
                                                       fast_sigmoid(v1));
                        if (set == 0) *(__half2*)&gZ[base + n] = h2;
                        else          *(__half2*)&gS[base + n] = h2;
                    }
                }
            }
        }
    }
}

// ---------------------------------------------------------------------------
// Vertical scan phase A: per-segment affine composition (A,B) over 32 rows.
// grid: 4096 blocks x 256 thr; block = seg(8) | c(64) | b(4) | g(2).
// ---------------------------------------------------------------------------
__global__ __launch_bounds__(256)
void segscan_v_kernel()
{
    const int x   = threadIdx.x;
    const int blk = blockIdx.x;
    const int seg = blk & 7;
    const int c   = (blk >> 3) & 63;
    const int b   = (blk >> 9) & 3;
    const int g   = blk >> 11;

    const size_t pb = (((size_t)b * C4 + g * 64 + c) << 16) + x;

    float A = 1.f, Bv = 0.f;
    const int ybase = seg << 5;
    if (g == 0) {
#pragma unroll 8
        for (int i = 0; i < 32; ++i) {
            size_t off = (size_t)(ybase + i) << 8;
            float z  = __half2float(gZ[pb + off]);
            float hv = __half2float(gH[pb + off]);
            float ai = 1.f - z;
            Bv = fmaf(ai, Bv, z * hv);
            A  = A * ai;
        }
    } else {
#pragma unroll 8
        for (int i = 31; i >= 0; --i) {
            size_t off = (size_t)(ybase + i) << 8;
            float z  = __half2float(gZ[pb + off]);
            float hv = __half2float(gH[pb + off]);
            float ai = 1.f - z;
            Bv = fmaf(ai, Bv, z * hv);
            A  = A * ai;
        }
    }
    gSeg[(size_t)blk * 256 + x] = make_float2(A, Bv);
}

// ---------------------------------------------------------------------------
// Fused tail: vertical apply (groups 0,1) into smem, then horizontal scans
// (groups 2,3) per row, single write of out. Block = seg(8) | c(64) | b(4).
// ---------------------------------------------------------------------------
__global__ __launch_bounds__(256)
void scan_tail_kernel(const float* __restrict__ h20,
                      const float* __restrict__ h21,
                      const float* __restrict__ h30,
                      const float* __restrict__ h31,
                      float* __restrict__ out)
{
    __shared__ float Sbuf[256][33];

    const int blk = blockIdx.x;
    const int seg = blk & 7;
    const int c   = (blk >> 3) & 63;
    const int b   = blk >> 9;
    const int tid = threadIdx.x;
    const int warp = tid >> 5;
    const int lane = tid & 31;

    // ================= part 1: vertical apply for column x = tid ===========
    {
        const int x = tid;
        float st0 = h20[c];
        {
            const size_t base = ((size_t)((0 * 4 + b) * 64 + c) * 8) * 256 + x;
            for (int k = 0; k < seg; ++k) {
                float2 f = gSeg[base + (size_t)k * 256];
                st0 = fmaf(f.x, st0, f.y);
            }
        }
        float st1 = h21[c];
        {
            const size_t base = ((size_t)((1 * 4 + b) * 64 + c) * 8) * 256 + x;
            for (int k = 7; k > seg; --k) {
                float2 f = gSeg[base + (size_t)k * 256];
                st1 = fmaf(f.x, st1, f.y);
            }
        }

        const int ybase = seg << 5;
        const size_t p0 = (((size_t)b * C4 + c) << 16) + x;         // group 0
        const size_t p1 = p0 + ((size_t)64 << 16);                  // group 1

#pragma unroll
        for (int i = 0; i < 32; ++i) {
            size_t off = (size_t)(ybase + i) << 8;
            float z  = __half2float(gZ[p0 + off]);
            float hv = __half2float(gH[p0 + off]);
            float s  = __half2float(gS[p0 + off]);
            st0 = z * hv + (1.f - z) * st0;
            Sbuf[x][i] = s * st0;
        }
#pragma unroll
        for (int i = 31; i >= 0; --i) {
            size_t off = (size_t)(ybase + i) << 8;
            float z  = __half2float(gZ[p1 + off]);
            float hv = __half2float(gH[p1 + off]);
            float s  = __half2float(gS[p1 + off]);
            st1 = z * hv + (1.f - z) * st1;
            Sbuf[x][i] += s * st1;
        }
    }
    __syncthreads();

    // ================= part 2: horizontal scans, rows of this seg ==========
    const float hi30 = h30[c];
    const float hi31 = h31[c];
    const size_t p2 = ((size_t)b * C4 + 128 + c) << 16;             // group 2
    const size_t p3 = ((size_t)b * C4 + 192 + c) << 16;             // group 3
    const size_t ob = ((size_t)b * 64 + c) << 16;

    for (int rr = 0; rr < 4; ++rr) {
        const int rloc = warp * 4 + rr;                 // 0..31
        const int y = (seg << 5) + rloc;
        const size_t ro = ((size_t)y << 8) + lane * 8;

        float res[8];

        // ---- group 2: forward scan ----
        {
            float zz[8], qq[8], ss[8];
            ld8h(&gZ[p2 + ro], zz);
            ld8h(&gH[p2 + ro], qq);
            float A[8], Bv[8];
            float ra = 1.f, rb = 0.f;
#pragma unroll
            for (int i = 0; i < 8; ++i) {
                float ai = 1.f - zz[i];
                float bi = zz[i] * qq[i];
                rb = fmaf(ai, rb, bi);
                ra = ra * ai;
                A[i] = ra; Bv[i] = rb;
            }
            float ga = ra, gb = rb;
#pragma unroll
            for (int off = 1; off < 32; off <<= 1) {
                float pa = __shfl_up_sync(0xFFFFFFFFu, ga, off);
                float pb = __shfl_up_sync(0xFFFFFFFFu, gb, off);
                if (lane >= off) { gb = fmaf(ga, pb, gb); ga = ga * pa; }
            }
            float PA = __shfl_up_sync(0xFFFFFFFFu, ga, 1);
            float PB = __shfl_up_sync(0xFFFFFFFFu, gb, 1);
            if (lane == 0) { PA = 1.f; PB = 0.f; }
            float base = fmaf(PA, hi30, PB);
            ld8h(&gS[p2 + ro], ss);
#pragma unroll
            for (int i = 0; i < 8; ++i)
                res[i] = ss[i] * fmaf(A[i], base, Bv[i]);
        }

        // ---- group 3: reverse scan ----
        {
            float zz[8], qq[8], ss[8];
            ld8h(&gZ[p3 + ro], zz);
            ld8h(&gH[p3 + ro], qq);
            float A[8], Bv[8];
            float ra = 1.f, rb = 0.f;
#pragma unroll
            for (int i = 7; i >= 0; --i) {
                float ai = 1.f - zz[i];
                float bi = zz[i] * qq[i];
                rb = fmaf(ai, rb, bi);
                ra = ra * ai;
                A[i] = ra; Bv[i] = rb;
            }
            float ga = ra, gb = rb;
#pragma unroll
            for (int off = 1; off < 32; off <<= 1) {
                float pa = __shfl_down_sync(0xFFFFFFFFu, ga, off);
                float pb = __shfl_down_sync(0xFFFFFFFFu, gb, off);
                if (lane + off < 32) { gb = fmaf(ga, pb, gb); ga = ga * pa; }
            }
            float PA = __shfl_down_sync(0xFFFFFFFFu, ga, 1);
            float PB = __shfl_down_sync(0xFFFFFFFFu, gb, 1);
            if (lane == 31) { PA = 1.f; PB = 0.f; }
            float base = fmaf(PA, hi31, PB);
            ld8h(&gS[p3 + ro], ss);
#pragma unroll
            for (int i = 0; i < 8; ++i)
                res[i] += ss[i] * fmaf(A[i], base, Bv[i]);
        }

        // ---- add vertical part from smem, single store ----
        float4 olo, ohi;
        olo.x = res[0] + Sbuf[lane * 8 + 0][rloc];
        olo.y = res[1] + Sbuf[lane * 8 + 1][rloc];
        olo.z = res[2] + Sbuf[lane * 8 + 2][rloc];
        olo.w = res[3] + Sbuf[lane * 8 + 3][rloc];
        ohi.x = res[4] + Sbuf[lane * 8 + 4][rloc];
        ohi.y = res[5] + Sbuf[lane * 8 + 5][rloc];
        ohi.z = res[6] + Sbuf[lane * 8 + 6][rloc];
        ohi.w = res[7] + Sbuf[lane * 8 + 7][rloc];
        *(float4*)&out[ob + ro]     = olo;
        *(float4*)&out[ob + ro + 4] = ohi;
    }
}

// ---------------------------------------------------------------------------
extern "C" void kernel_launch(void* const* d_in, const int* in_sizes, int n_in,
                              void* d_out, int out_size)
{
    const float* xs = (const float*)d_in[0];

    ConvParams P;
    for (int s = 0; s < 3; ++s) {
        int base = 1 + s * 5;
        P.w[s] = (const float*)d_in[base + 0];
        P.g[s] = (const float*)d_in[base + 1];
        P.b[s] = (const float*)d_in[base + 2];
        P.m[s] = (const float*)d_in[base + 3];
        P.v[s] = (const float*)d_in[base + 4];
    }
    const float* h20 = (const float*)d_in[16];
    const float* h21 = (const float*)d_in[17];
    const float* h30 = (const float*)d_in[18];
    const float* h31 = (const float*)d_in[19];

    float* out = (float*)d_out;

    cudaFuncSetAttribute(conv_mma_kernel,
                         cudaFuncAttributeMaxDynamicSharedMemorySize, SMEM_BYTES);

    dim3 xgrid(2, 256, 4);
    xpose_kernel<<<xgrid, 256>>>(xs);

    prep_kernel<<<1728, 256>>>(P);

    dim3 cgrid(512, 4);
    conv_mma_kernel<<<cgrid, 256, SMEM_BYTES>>>();

    segscan_v_kernel<<<4096, 256>>>();
    scan_tail_kernel<<<2048, 256>>>(h20, h21, h30, h31, out);
}

// round 12
// speedup vs baseline: 1.0200x; 1.0200x over previous
#include <cuda_runtime.h>
#include <cuda_fp16.h>
#include <math.h>
#include <stdint.h>

// ---------------------------------------------------------------------------
// MiniGRUConv2d4 on GB300 (compute_103 PTX target -> legacy mma.sync path):
//   pass 1: fused (transpose xs -> xh fp16) + (fold BN into fp16 weights)
//   pass 2: 3x(conv3x3+BN[+sigmoid]) implicit GEMM, fp16 mma.sync.m16n8k16,
//           ldmatrix loads w/ one-ahead B-fragment prefetch, fp16 planes.
//   pass 3: vertical scans: segment compose + fused apply/horizontal tail.
// ---------------------------------------------------------------------------

#define B_  4
#define CIN 64
#define C4  256

static __device__ __half gH[(size_t)B_ * C4 * 256 * 256];            // h plane
static __device__ __half gZ[(size_t)B_ * C4 * 256 * 256];            // z plane
static __device__ __half gS[(size_t)B_ * C4 * 256 * 256];            // s plane
static __device__ __align__(16) __half gXh[(size_t)B_ * 256 * 256 * 64];
static __device__ __align__(16) __half gWtH[768 * 576];
static __device__ float gBias[768];
static __device__ float2 gSeg[2 * 4 * 64 * 8 * 256];                 // seg (A,B)

struct ConvParams {
    const float* w[3];
    const float* g[3];
    const float* b[3];
    const float* m[3];
    const float* v[3];
};

// ---------------- fast sigmoid (no MUFU) ------------------------------------
__device__ __forceinline__ float fast_sigmoid(float x)
{
    float u = -1.44269504f * x;
    u = fminf(fmaxf(u, -60.f), 60.f);
    float fi = rintf(u);
    float f  = u - fi;
    float p = 1.54035304e-4f;
    p = fmaf(p, f, 1.33335581e-3f);
    p = fmaf(p, f, 9.61812910e-3f);
    p = fmaf(p, f, 5.55041087e-2f);
    p = fmaf(p, f, 2.40226507e-1f);
    p = fmaf(p, f, 6.93147181e-1f);
    p = fmaf(p, f, 1.0f);
    int ei = (int)fi;
    float e = __int_as_float(__float_as_int(p) + (ei << 23));
    float d = 1.0f + e;
    float r = __int_as_float(0x7EF311C3 - __float_as_int(d));
    r = r * (2.0f - d * r);
    r = r * (2.0f - d * r);
    r = r * (2.0f - d * r);
    return r;
}

// ---------------- small helpers ---------------------------------------------
__device__ __forceinline__ uint32_t smem_u32(const void* p)
{
    uint32_t a;
    asm("{ .reg .u64 t; cvta.to.shared.u64 t, %1; cvt.u32.u64 %0, t; }"
        : "=r"(a) : "l"(p));
    return a;
}
__device__ __forceinline__ void cp16(uint32_t dst, const void* src)
{
    size_t g = __cvta_generic_to_global(src);
    asm volatile("cp.async.cg.shared.global [%0], [%1], 16;"
                 :: "r"(dst), "l"(g) : "memory");
}
__device__ __forceinline__ void sts_zero16(uint32_t a)
{
    asm volatile("st.shared.v4.u32 [%0], {%1,%1,%1,%1};" :: "r"(a), "r"(0u) : "memory");
}
__device__ __forceinline__ void ldsm_x4(uint32_t& r0, uint32_t& r1,
                                        uint32_t& r2, uint32_t& r3, uint32_t a)
{
    asm volatile("ldmatrix.sync.aligned.m8n8.x4.shared.b16 {%0,%1,%2,%3}, [%4];"
                 : "=r"(r0), "=r"(r1), "=r"(r2), "=r"(r3) : "r"(a));
}
// load 8 consecutive halves -> 8 floats
__device__ __forceinline__ void ld8h(const __half* p, float* d)
{
    uint4 u = *(const uint4*)p;
    const __half2* h = (const __half2*)&u;
    float2 f0 = __half22float2(h[0]);
    float2 f1 = __half22float2(h[1]);
    float2 f2 = __half22float2(h[2]);
    float2 f3 = __half22float2(h[3]);
    d[0] = f0.x; d[1] = f0.y; d[2] = f1.x; d[3] = f1.y;
    d[4] = f2.x; d[5] = f2.y; d[6] = f3.x; d[7] = f3.y;
}

// ---------------------------------------------------------------------------
// Fused prep: blocks [0,2048) transpose xs -> gXh; blocks [2048,3776) fold BN
// weights -> gWtH (+ bias).
// ---------------------------------------------------------------------------
__global__ __launch_bounds__(256)
void prep_fused_kernel(const float* __restrict__ xs, ConvParams P)
{
    const int blk = blockIdx.x;
    const int tid = threadIdx.x;

    if (blk >= 2048) {
        int idx = (blk - 2048) * 256 + tid;
        if (idx < 768) {
            int set = idx >> 8, co = idx & 255;
            float inv = P.g[set][co] * rsqrtf(P.v[set][co] + 1e-5f);
            gBias[idx] = P.b[set][co] - P.m[set][co] * inv;
        }
        if (idx < 768 * 576) {
            int co_g = idx / 576;
            int k    = idx - co_g * 576;
            int r    = k >> 6;
            int ci   = k & 63;
            int set  = co_g >> 8;
            int co   = co_g & 255;
            float inv = P.g[set][co] * rsqrtf(P.v[set][co] + 1e-5f);
            gWtH[idx] = __float2half_rn(P.w[set][(co * 64 + ci) * 9 + r] * inv);
        }
        return;
    }

    __shared__ float S[64][129];
    const int xt = blk & 1;
    const int y  = (blk >> 1) & 255;
    const int b  = blk >> 9;

    const float* src = xs + (((size_t)b * CIN) << 16) + (y << 8) + xt * 128;
#pragma unroll
    for (int p = 0; p < 8; ++p) {
        int idx = tid + (p << 8);
        int ci  = idx >> 5;
        int x4  = idx & 31;
        float4 v = *(const float4*)(src + (((size_t)ci) << 16) + (x4 << 2));
        S[ci][x4 * 4 + 0] = v.x;
        S[ci][x4 * 4 + 1] = v.y;
        S[ci][x4 * 4 + 2] = v.z;
        S[ci][x4 * 4 + 3] = v.w;
    }
    __syncthreads();

    __half* dst = gXh + ((((size_t)b * 256 + y) * 256) + xt * 128) * 64;
#pragma unroll
    for (int p = 0; p < 4; ++p) {
        int chunk = tid + (p << 8);
        int g = chunk & 7;
        int x = chunk >> 3;
        int c0 = g * 8;
        __half2 h0 = __floats2half2_rn(S[c0 + 0][x], S[c0 + 1][x]);
        __half2 h1 = __floats2half2_rn(S[c0 + 2][x], S[c0 + 3][x]);
        __half2 h2 = __floats2half2_rn(S[c0 + 4][x], S[c0 + 5][x]);
        __half2 h3 = __floats2half2_rn(S[c0 + 6][x], S[c0 + 7][x]);
        uint4 val;
        val.x = *(uint32_t*)&h0; val.y = *(uint32_t*)&h1;
        val.z = *(uint32_t*)&h2; val.w = *(uint32_t*)&h3;
        *(uint4*)(dst + (size_t)x * 64 + g * 8) = val;
    }
}

// ---------------------------------------------------------------------------
// Conv: CTA = 128 px x 128 couts, 8 warps (4m x 2n), warp 32co x 64px.
// ldmatrix loads with one-ahead B prefetch; progressive halo; 2 CTAs/SM.
// ---------------------------------------------------------------------------
#define BT_STRIDE 132
#define BT_BYTES  (3 * BT_STRIDE * 128)          // 50688
#define A_BUF     8192
#define SMEM_BYTES (BT_BYTES + 4 * A_BUF)        // 83456

__global__ __launch_bounds__(256, 2)
void conv_mma_kernel()
{
    extern __shared__ char smem[];
    const uint32_t sB = smem_u32(smem);
    const uint32_t sA = sB + BT_BYTES;

    const int tid = threadIdx.x;
    const int l   = tid & 31;
    const int w   = tid >> 5;
    const int wm  = w >> 1;            // 0..3 (32 co each)
    const int wn  = w & 1;             // 0..1 (64 px each)

    const int bx = blockIdx.x;         // 0..511
    const int y0 = bx >> 1;
    const int x0 = (bx & 1) << 7;
    const int m0 = blockIdx.y << 7;    // 0..640
    const int b  = blockIdx.z;

    // ---- A ring producer: 128co x 32k fp16 per chunk ----
    auto issueA = [&](int kt2) {
        if (kt2 < 18) {
            uint32_t base = sA + (uint32_t)((kt2 & 3) * A_BUF);
            const __half* src = gWtH + (size_t)m0 * 576 + kt2 * 32;
#pragma unroll
            for (int p = 0; p < 2; ++p) {
                int chunk = tid + (p << 8);
                int co  = chunk >> 2;
                int kpg = chunk & 3;
                uint32_t wrd = (uint32_t)(co << 4)
                             + (uint32_t)((kpg ^ ((co >> 1) & 3)) << 2);
                cp16(base + (wrd << 2), src + (size_t)co * 576 + (kpg << 3));
            }
        }
        asm volatile("cp.async.commit_group;" ::: "memory");
    };

    // ---- progressive B halo fill: row r goes in cp.async group r ----
    for (int row = 0; row < 3; ++row) {
        const int y = y0 - 1 + row;
        const bool rok = (unsigned)y < 256u;
        for (int t = tid; t < 1040; t += 256) {
            int slot = t >> 3;
            int g    = t & 7;
            int x    = x0 + slot - 1;
            uint32_t dst = sB + (uint32_t)(row * BT_STRIDE + slot) * 128
                         + (uint32_t)((g ^ (slot & 7)) << 4);
            if (rok && (unsigned)x < 256u)
                cp16(dst, gXh + ((((size_t)b * 256 + y) * 256 + x) * 64 + g * 8));
            else
                sts_zero16(dst);
        }
        issueA(row);
    }

    // ---- per-lane ldmatrix address constants ----
    const int hiA   = l >> 4;
    const int cA0   = (wm << 5) + (l & 15);
    const int cA1   = cA0 + 16;
    const int xa0   = (cA0 >> 1) & 3;
    const int xa1   = (cA1 >> 1) & 3;
    const uint32_t aoff0 = (uint32_t)(cA0 << 6);
    const uint32_t aoff1 = (uint32_t)(cA1 << 6);
    const int gsel  = (l >> 3) & 1;
    const int sbl   = (wn << 6) + (l & 7) + ((l >> 4) << 3);

    float acc[2][8][4];
#pragma unroll
    for (int mt = 0; mt < 2; ++mt)
#pragma unroll
        for (int nt = 0; nt < 8; ++nt)
#pragma unroll
            for (int c = 0; c < 4; ++c) acc[mt][nt][c] = 0.f;

    for (int kt = 0; kt < 18; ++kt) {
        asm volatile("cp.async.wait_group 2;" ::: "memory");
        __syncthreads();

        const uint32_t abuf = sA + (uint32_t)((kt & 3) * A_BUF);
        const int r   = kt >> 1;
        const int row = r / 3;
        const int dxp = r - row * 3;
        const uint32_t rowbase = sB + (uint32_t)(row * BT_STRIDE) * 128;

#pragma unroll
        for (int ks = 0; ks < 2; ++ks) {
            const int kg = (ks << 1) + hiA;
            uint32_t a0[4], a1[4];
            ldsm_x4(a0[0], a0[1], a0[2], a0[3],
                    abuf + aoff0 + (uint32_t)((kg ^ xa0) << 4));
            ldsm_x4(a1[0], a1[1], a1[2], a1[3],
                    abuf + aoff1 + (uint32_t)((kg ^ xa1) << 4));

            const int ga = ((kt & 1) << 2) + (ks << 1) + gsel;
            auto baddr = [&](int ntp) {
                int slot = sbl + (ntp << 4) + dxp;
                return rowbase + (uint32_t)(slot << 7)
                     + (uint32_t)((ga ^ (slot & 7)) << 4);
            };

            // one-ahead B-fragment prefetch pipeline
            uint32_t bc[4], bn[4];
            ldsm_x4(bc[0], bc[1], bc[2], bc[3], baddr(0));
#pragma unroll
            for (int ntp = 0; ntp < 4; ++ntp) {
                if (ntp < 3)
                    ldsm_x4(bn[0], bn[1], bn[2], bn[3], baddr(ntp + 1));

                const int nt0 = ntp << 1;
#pragma unroll
                for (int half = 0; half < 2; ++half) {
                    uint32_t bb0 = half ? bc[2] : bc[0];
                    uint32_t bb1 = half ? bc[3] : bc[1];
                    int nt = nt0 + half;
                    asm volatile(
                        "mma.sync.aligned.m16n8k16.row.col.f32.f16.f16.f32 "
                        "{%0,%1,%2,%3}, {%4,%5,%6,%7}, {%8,%9}, {%0,%1,%2,%3};"
                        : "+f"(acc[0][nt][0]), "+f"(acc[0][nt][1]),
                          "+f"(acc[0][nt][2]), "+f"(acc[0][nt][3])
                        : "r"(a0[0]), "r"(a0[1]), "r"(a0[2]), "r"(a0[3]),
                          "r"(bb0), "r"(bb1));
                    asm volatile(
                        "mma.sync.aligned.m16n8k16.row.col.f32.f16.f16.f32 "
                        "{%0,%1,%2,%3}, {%4,%5,%6,%7}, {%8,%9}, {%0,%1,%2,%3};"
                        : "+f"(acc[1][nt][0]), "+f"(acc[1][nt][1]),
                          "+f"(acc[1][nt][2]), "+f"(acc[1][nt][3])
                        : "r"(a1[0]), "r"(a1[1]), "r"(a1[2]), "r"(a1[3]),
                          "r"(bb0), "r"(bb1));
                }
#pragma unroll
                for (int q = 0; q < 4; ++q) bc[q] = bn[q];
            }
        }
        issueA(kt + 3);
    }

    // ---- epilogue: bias; all sets -> fp16 planes (sigmoid for sets 0/2) ----
    const int set = m0 >> 8;
    const int chb = m0 & 255;
#pragma unroll
    for (int mt = 0; mt < 2; ++mt) {
#pragma unroll
        for (int rr = 0; rr < 2; ++rr) {
            int cloc = (wm << 5) + (mt << 4) + (l >> 2) + (rr << 3);
            float bias = gBias[m0 + cloc];
            int ch = chb + cloc;
            size_t base = (((size_t)b * C4 + ch) << 16) + ((size_t)y0 << 8) + x0;
#pragma unroll
            for (int nt = 0; nt < 8; ++nt) {
                int n = (wn << 6) + (nt << 3) + ((l & 3) << 1);
                float v0 = acc[mt][nt][rr * 2 + 0] + bias;
                float v1 = acc[mt][nt][rr * 2 + 1] + bias;
                if (set == 1) {
                    *(__half2*)&gH[base + n] = __floats2half2_rn(v0, v1);
                } else {
                    __half2 h2 = __floats2half2_rn(fast_sigmoid(v0),
                                                   fast_sigmoid(v1));
                    if (set == 0) *(__half2*)&gZ[base + n] = h2;
                    else          *(__half2*)&gS[base + n] = h2;
                }
            }
        }
    }
}

// ---------------------------------------------------------------------------
// Vertical scan phase A: per-segment affine composition (A,B) over 32 rows.
// ---------------------------------------------------------------------------
__global__ __launch_bounds__(256)
void segscan_v_kernel()
{
    const int x   = threadIdx.x;
    const int blk = blockIdx.x;
    const int seg = blk & 7;
    const int c   = (blk >> 3) & 63;
    const int b   = (blk >> 9) & 3;
    const int g   = blk >> 11;

    const size_t pb = (((size_t)b * C4 + g * 64 + c) << 16) + x;

    float A = 1.f, Bv = 0.f;
    const int ybase = seg << 5;
    if (g == 0) {
#pragma unroll 8
        for (int i = 0; i < 32; ++i) {
            size_t off = (size_t)(ybase + i) << 8;
            float z  = __half2float(gZ[pb + off]);
            float hv = __half2float(gH[pb + off]);
            float ai = 1.f - z;
            Bv = fmaf(ai, Bv, z * hv);
            A  = A * ai;
        }
    } else {
#pragma unroll 8
        for (int i = 31; i >= 0; --i) {
            size_t off = (size_t)(ybase + i) << 8;
            float z  = __half2float(gZ[pb + off]);
            float hv = __half2float(gH[pb + off]);
            float ai = 1.f - z;
            Bv = fmaf(ai, Bv, z * hv);
            A  = A * ai;
        }
    }
    gSeg[(size_t)blk * 256 + x] = make_float2(A, Bv);
}

// ---------------------------------------------------------------------------
// Fused tail: vertical apply (groups 0,1) into smem, then horizontal scans
// (groups 2,3) per row, single write of out.
// ---------------------------------------------------------------------------
__global__ __launch_bounds__(256)
void scan_tail_kernel(const float* __restrict__ h20,
                      const float* __restrict__ h21,
                      const float* __restrict__ h30,
                      const float* __restrict__ h31,
                      float* __restrict__ out)
{
    __shared__ float Sbuf[256][33];

    const int blk = blockIdx.x;
    const int seg = blk & 7;
    const int c   = (blk >> 3) & 63;
    const int b   = blk >> 9;
    const int tid = threadIdx.x;
    const int warp = tid >> 5;
    const int lane = tid & 31;

    // ================= part 1: vertical apply for column x = tid ===========
    {
        const int x = tid;
        float st0 = h20[c];
        {
            const size_t base = ((size_t)((0 * 4 + b) * 64 + c) * 8) * 256 + x;
            for (int k = 0; k < seg; ++k) {
                float2 f = gSeg[base + (size_t)k * 256];
                st0 = fmaf(f.x, st0, f.y);
            }
        }
        float st1 = h21[c];
        {
            const size_t base = ((size_t)((1 * 4 + b) * 64 + c) * 8) * 256 + x;
            for (int k = 7; k > seg; --k) {
                float2 f = gSeg[base + (size_t)k * 256];
                st1 = fmaf(f.x, st1, f.y);
            }
        }

        const int ybase = seg << 5;
        const size_t p0 = (((size_t)b * C4 + c) << 16) + x;
        const size_t p1 = p0 + ((size_t)64 << 16);

#pragma unroll
        for (int i = 0; i < 32; ++i) {
            size_t off = (size_t)(ybase + i) << 8;
            float z  = __half2float(gZ[p0 + off]);
            float hv = __half2float(gH[p0 + off]);
            float s  = __half2float(gS[p0 + off]);
            st0 = z * hv + (1.f - z) * st0;
            Sbuf[x][i] = s * st0;
        }
#pragma unroll
        for (int i = 31; i >= 0; --i) {
            size_t off = (size_t)(ybase + i) << 8;
            float z  = __half2float(gZ[p1 + off]);
            float hv = __half2float(gH[p1 + off]);
            float s  = __half2float(gS[p1 + off]);
            st1 = z * hv + (1.f - z) * st1;
            Sbuf[x][i] += s * st1;
        }
    }
    __syncthreads();

    // ================= part 2: horizontal scans ============================
    const float hi30 = h30[c];
    const float hi31 = h31[c];
    const size_t p2 = ((size_t)b * C4 + 128 + c) << 16;
    const size_t p3 = ((size_t)b * C4 + 192 + c) << 16;
    const size_t ob = ((size_t)b * 64 + c) << 16;

    for (int rr = 0; rr < 4; ++rr) {
        const int rloc = warp * 4 + rr;
        const int y = (seg << 5) + rloc;
        const size_t ro = ((size_t)y << 8) + lane * 8;

        float res[8];

        // ---- group 2: forward scan ----
        {
            float zz[8], qq[8], ss[8];
            ld8h(&gZ[p2 + ro], zz);
            ld8h(&gH[p2 + ro], qq);
            float A[8], Bv[8];
            float ra = 1.f, rb = 0.f;
#pragma unroll
            for (int i = 0; i < 8; ++i) {
                float ai = 1.f - zz[i];
                float bi = zz[i] * qq[i];
                rb = fmaf(ai, rb, bi);
                ra = ra * ai;
                A[i] = ra; Bv[i] = rb;
            }
            float ga = ra, gb = rb;
#pragma unroll
            for (int off = 1; off < 32; off <<= 1) {
                float pa = __shfl_up_sync(0xFFFFFFFFu, ga, off);
                float pb = __shfl_up_sync(0xFFFFFFFFu, gb, off);
                if (lane >= off) { gb = fmaf(ga, pb, gb); ga = ga * pa; }
            }
            float PA = __shfl_up_sync(0xFFFFFFFFu, ga, 1);
            float PB = __shfl_up_sync(0xFFFFFFFFu, gb, 1);
            if (lane == 0) { PA = 1.f; PB = 0.f; }
            float base = fmaf(PA, hi30, PB);
            ld8h(&gS[p2 + ro], ss);
#pragma unroll
            for (int i = 0; i < 8; ++i)
                res[i] = ss[i] * fmaf(A[i], base, Bv[i]);
        }

        // ---- group 3: reverse scan ----
        {
            float zz[8], qq[8], ss[8];
            ld8h(&gZ[p3 + ro], zz);
            ld8h(&gH[p3 + ro], qq);
            float A[8], Bv[8];
            float ra = 1.f, rb = 0.f;
#pragma unroll
            for (int i = 7; i >= 0; --i) {
                float ai = 1.f - zz[i];
                float bi = zz[i] * qq[i];
                rb = fmaf(ai, rb, bi);
                ra = ra * ai;
                A[i] = ra; Bv[i] = rb;
            }
            float ga = ra, gb = rb;
#pragma unroll
            for (int off = 1; off < 32; off <<= 1) {
                float pa = __shfl_down_sync(0xFFFFFFFFu, ga, off);
                float pb = __shfl_down_sync(0xFFFFFFFFu, gb, off);
                if (lane + off < 32) { gb = fmaf(ga, pb, gb); ga = ga * pa; }
            }
            float PA = __shfl_down_sync(0xFFFFFFFFu, ga, 1);
            float PB = __shfl_down_sync(0xFFFFFFFFu, gb, 1);
            if (lane == 31) { PA = 1.f; PB = 0.f; }
            float base = fmaf(PA, hi31, PB);
            ld8h(&gS[p3 + ro], ss);
#pragma unroll
            for (int i = 0; i < 8; ++i)
                res[i] += ss[i] * fmaf(A[i], base, Bv[i]);
        }

        float4 olo, ohi;
        olo.x = res[0] + Sbuf[lane * 8 + 0][rloc];
        olo.y = res[1] + Sbuf[lane * 8 + 1][rloc];
        olo.z = res[2] + Sbuf[lane * 8 + 2][rloc];
        olo.w = res[3] + Sbuf[lane * 8 + 3][rloc];
        ohi.x = res[4] + Sbuf[lane * 8 + 4][rloc];
        ohi.y = res[5] + Sbuf[lane * 8 + 5][rloc];
        ohi.z = res[6] + Sbuf[lane * 8 + 6][rloc];
        ohi.w = res[7] + Sbuf[lane * 8 + 7][rloc];
        *(float4*)&out[ob + ro]     = olo;
        *(float4*)&out[ob + ro + 4] = ohi;
    }
}

// ---------------------------------------------------------------------------
extern "C" void kernel_launch(void* const* d_in, const int* in_sizes, int n_in,
                              void* d_out, int out_size)
{
    const float* xs = (const float*)d_in[0];

    ConvParams P;
    for (int s = 0; s < 3; ++s) {
        int base = 1 + s * 5;
        P.w[s] = (const float*)d_in[base + 0];
        P.g[s] = (const float*)d_in[base + 1];
        P.b[s] = (const float*)d_in[base + 2];
        P.m[s] = (const float*)d_in[base + 3];
        P.v[s] = (const float*)d_in[base + 4];
    }
    const float* h20 = (const float*)d_in[16];
    const float* h21 = (const float*)d_in[17];
    const float* h30 = (const float*)d_in[18];
    const float* h31 = (const float*)d_in[19];

    float* out = (float*)d_out;

    cudaFuncSetAttribute(conv_mma_kernel,
                         cudaFuncAttributeMaxDynamicSharedMemorySize, SMEM_BYTES);

    prep_fused_kernel<<<2048 + 1728, 256>>>(xs, P);

    dim3 cgrid(512, 6, 4);
    conv_mma_kernel<<<cgrid, 256, SMEM_BYTES>>>();

    segscan_v_kernel<<<4096, 256>>>();
    scan_tail_kernel<<<2048, 256>>>(h20, h21, h30, h31, out);
}

// round 13
// speedup vs baseline: 1.1464x; 1.1240x over previous
#include <cuda_runtime.h>
#include <cuda_fp16.h>
#include <math.h>
#include <stdint.h>

// ---------------------------------------------------------------------------
// MiniGRUConv2d4 on GB300 (compute_103 PTX target -> legacy mma.sync path):
//   pass 1: fused (transpose xs -> xh fp16) + (fold BN into fp16 weights)
//   pass 2: 3x(conv3x3+BN[+sigmoid]) implicit GEMM, fp16 mma.sync.m16n8k16,
//           6-deep A ring, ONE syncthreads per 2 k-steps, fp16 planes.
//   pass 3: vertical scans: segment compose + fused apply/horizontal tail.
// ---------------------------------------------------------------------------

#define B_  4
#define CIN 64
#define C4  256

static __device__ __half gH[(size_t)B_ * C4 * 256 * 256];            // h plane
static __device__ __half gZ[(size_t)B_ * C4 * 256 * 256];            // z plane
static __device__ __half gS[(size_t)B_ * C4 * 256 * 256];            // s plane
static __device__ __align__(16) __half gXh[(size_t)B_ * 256 * 256 * 64];
static __device__ __align__(16) __half gWtH[768 * 576];
static __device__ float gBias[768];
static __device__ float2 gSeg[2 * 4 * 64 * 8 * 256];                 // seg (A,B)

struct ConvParams {
    const float* w[3];
    const float* g[3];
    const float* b[3];
    const float* m[3];
    const float* v[3];
};

// ---------------- fast sigmoid (no MUFU) ------------------------------------
__device__ __forceinline__ float fast_sigmoid(float x)
{
    float u = -1.44269504f * x;
    u = fminf(fmaxf(u, -60.f), 60.f);
    float fi = rintf(u);
    float f  = u - fi;
    float p = 1.54035304e-4f;
    p = fmaf(p, f, 1.33335581e-3f);
    p = fmaf(p, f, 9.61812910e-3f);
    p = fmaf(p, f, 5.55041087e-2f);
    p = fmaf(p, f, 2.40226507e-1f);
    p = fmaf(p, f, 6.93147181e-1f);
    p = fmaf(p, f, 1.0f);
    int ei = (int)fi;
    float e = __int_as_float(__float_as_int(p) + (ei << 23));
    float d = 1.0f + e;
    float r = __int_as_float(0x7EF311C3 - __float_as_int(d));
    r = r * (2.0f - d * r);
    r = r * (2.0f - d * r);
    r = r * (2.0f - d * r);
    return r;
}

// ---------------- small helpers ---------------------------------------------
__device__ __forceinline__ uint32_t smem_u32(const void* p)
{
    uint32_t a;
    asm("{ .reg .u64 t; cvta.to.shared.u64 t, %1; cvt.u32.u64 %0, t; }"
        : "=r"(a) : "l"(p));
    return a;
}
__device__ __forceinline__ void cp16(uint32_t dst, const void* src)
{
    size_t g = __cvta_generic_to_global(src);
    asm volatile("cp.async.cg.shared.global [%0], [%1], 16;"
                 :: "r"(dst), "l"(g) : "memory");
}
__device__ __forceinline__ void sts_zero16(uint32_t a)
{
    asm volatile("st.shared.v4.u32 [%0], {%1,%1,%1,%1};" :: "r"(a), "r"(0u) : "memory");
}
__device__ __forceinline__ void ldsm_x4(uint32_t& r0, uint32_t& r1,
                                        uint32_t& r2, uint32_t& r3, uint32_t a)
{
    asm volatile("ldmatrix.sync.aligned.m8n8.x4.shared.b16 {%0,%1,%2,%3}, [%4];"
                 : "=r"(r0), "=r"(r1), "=r"(r2), "=r"(r3) : "r"(a));
}
// load 8 consecutive halves -> 8 floats
__device__ __forceinline__ void ld8h(const __half* p, float* d)
{
    uint4 u = *(const uint4*)p;
    const __half2* h = (const __half2*)&u;
    float2 f0 = __half22float2(h[0]);
    float2 f1 = __half22float2(h[1]);
    float2 f2 = __half22float2(h[2]);
    float2 f3 = __half22float2(h[3]);
    d[0] = f0.x; d[1] = f0.y; d[2] = f1.x; d[3] = f1.y;
    d[4] = f2.x; d[5] = f2.y; d[6] = f3.x; d[7] = f3.y;
}

// ---------------------------------------------------------------------------
// Fused prep: blocks [0,2048) transpose xs -> gXh; blocks [2048,3776) fold BN
// weights -> gWtH (+ bias).
// ---------------------------------------------------------------------------
__global__ __launch_bounds__(256)
void prep_fused_kernel(const float* __restrict__ xs, ConvParams P)
{
    const int blk = blockIdx.x;
    const int tid = threadIdx.x;

    if (blk >= 2048) {
        int idx = (blk - 2048) * 256 + tid;
        if (idx < 768) {
            int set = idx >> 8, co = idx & 255;
            float inv = P.g[set][co] * rsqrtf(P.v[set][co] + 1e-5f);
            gBias[idx] = P.b[set][co] - P.m[set][co] * inv;
        }
        if (idx < 768 * 576) {
            int co_g = idx / 576;
            int k    = idx - co_g * 576;
            int r    = k >> 6;
            int ci   = k & 63;
            int set  = co_g >> 8;
            int co   = co_g & 255;
            float inv = P.g[set][co] * rsqrtf(P.v[set][co] + 1e-5f);
            gWtH[idx] = __float2half_rn(P.w[set][(co * 64 + ci) * 9 + r] * inv);
        }
        return;
    }

    __shared__ float S[64][129];
    const int xt = blk & 1;
    const int y  = (blk >> 1) & 255;
    const int b  = blk >> 9;

    const float* src = xs + (((size_t)b * CIN) << 16) + (y << 8) + xt * 128;
#pragma unroll
    for (int p = 0; p < 8; ++p) {
        int idx = tid + (p << 8);
        int ci  = idx >> 5;
        int x4  = idx & 31;
        float4 v = *(const float4*)(src + (((size_t)ci) << 16) + (x4 << 2));
        S[ci][x4 * 4 + 0] = v.x;
        S[ci][x4 * 4 + 1] = v.y;
        S[ci][x4 * 4 + 2] = v.z;
        S[ci][x4 * 4 + 3] = v.w;
    }
    __syncthreads();

    __half* dst = gXh + ((((size_t)b * 256 + y) * 256) + xt * 128) * 64;
#pragma unroll
    for (int p = 0; p < 4; ++p) {
        int chunk = tid + (p << 8);
        int g = chunk & 7;
        int x = chunk >> 3;
        int c0 = g * 8;
        __half2 h0 = __floats2half2_rn(S[c0 + 0][x], S[c0 + 1][x]);
        __half2 h1 = __floats2half2_rn(S[c0 + 2][x], S[c0 + 3][x]);
        __half2 h2 = __floats2half2_rn(S[c0 + 4][x], S[c0 + 5][x]);
        __half2 h3 = __floats2half2_rn(S[c0 + 6][x], S[c0 + 7][x]);
        uint4 val;
        val.x = *(uint32_t*)&h0; val.y = *(uint32_t*)&h1;
        val.z = *(uint32_t*)&h2; val.w = *(uint32_t*)&h3;
        *(uint4*)(dst + (size_t)x * 64 + g * 8) = val;
    }
}

// ---------------------------------------------------------------------------
// Conv: CTA = 128 px x 128 couts, 8 warps (4m x 2n), warp 32co x 64px.
// ldmatrix fragment loads; 6-deep A ring; 1 sync per 2 kt; 2 CTAs/SM.
// ---------------------------------------------------------------------------
#define BT_STRIDE 132
#define BT_BYTES  (3 * BT_STRIDE * 128)          // 50688
#define A_BUF     8192
#define SMEM_BYTES (BT_BYTES + 6 * A_BUF)        // 99840

__global__ __launch_bounds__(256, 2)
void conv_mma_kernel()
{
    extern __shared__ char smem[];
    const uint32_t sB = smem_u32(smem);
    const uint32_t sA = sB + BT_BYTES;

    const int tid = threadIdx.x;
    const int l   = tid & 31;
    const int w   = tid >> 5;
    const int wm  = w >> 1;            // 0..3 (32 co each)
    const int wn  = w & 1;             // 0..1 (64 px each)

    const int bx = blockIdx.x;         // 0..511
    const int y0 = bx >> 1;
    const int x0 = (bx & 1) << 7;
    const int m0 = blockIdx.y << 7;    // 0..640
    const int b  = blockIdx.z;

    // ---- A ring producer: 128co x 32k fp16 per chunk; buffer = s % 6 ----
    auto issueA = [&](int s) {
        if (s < 18) {
            uint32_t base = sA + (uint32_t)((s % 6) * A_BUF);
            const __half* src = gWtH + (size_t)m0 * 576 + s * 32;
#pragma unroll
            for (int p = 0; p < 2; ++p) {
                int chunk = tid + (p << 8);
                int co  = chunk >> 2;
                int kpg = chunk & 3;
                uint32_t wrd = (uint32_t)(co << 4)
                             + (uint32_t)((kpg ^ ((co >> 1) & 3)) << 2);
                cp16(base + (wrd << 2), src + (size_t)co * 576 + (kpg << 3));
            }
        }
        asm volatile("cp.async.commit_group;" ::: "memory");
    };

    // ---- progressive B halo fill: row r goes in cp.async group r ----
    for (int row = 0; row < 3; ++row) {
        const int y = y0 - 1 + row;
        const bool rok = (unsigned)y < 256u;
        for (int t = tid; t < 1040; t += 256) {
            int slot = t >> 3;
            int g    = t & 7;
            int x    = x0 + slot - 1;
            uint32_t dst = sB + (uint32_t)(row * BT_STRIDE + slot) * 128
                         + (uint32_t)((g ^ (slot & 7)) << 4);
            if (rok && (unsigned)x < 256u)
                cp16(dst, gXh + ((((size_t)b * 256 + y) * 256 + x) * 64 + g * 8));
            else
                sts_zero16(dst);
        }
        issueA(row);
    }
    issueA(3);

    // ---- per-lane ldmatrix address constants ----
    const int hiA   = l >> 4;
    const int cA0   = (wm << 5) + (l & 15);
    const int cA1   = cA0 + 16;
    const int xa0   = (cA0 >> 1) & 3;
    const int xa1   = (cA1 >> 1) & 3;
    const uint32_t aoff0 = (uint32_t)(cA0 << 6);
    const uint32_t aoff1 = (uint32_t)(cA1 << 6);
    const int gsel  = (l >> 3) & 1;
    const int sbl   = (wn << 6) + (l & 7) + ((l >> 4) << 3);

    float acc[2][8][4];
#pragma unroll
    for (int mt = 0; mt < 2; ++mt)
#pragma unroll
        for (int nt = 0; nt < 8; ++nt)
#pragma unroll
            for (int c = 0; c < 4; ++c) acc[mt][nt][c] = 0.f;

    for (int ktp = 0; ktp < 18; ktp += 2) {
        asm volatile("cp.async.wait_group 2;" ::: "memory");
        __syncthreads();

        // kt pair shares r (= ktp>>1), hence same halo row and dx shift
        const int r   = ktp >> 1;
        const int row = r / 3;
        const int dxp = r - row * 3;
        const uint32_t rowbase = sB + (uint32_t)(row * BT_STRIDE) * 128;

#pragma unroll
        for (int sub = 0; sub < 2; ++sub) {
            const int kt = ktp + sub;
            const uint32_t abuf = sA + (uint32_t)((kt % 6) * A_BUF);

#pragma unroll
            for (int ks = 0; ks < 2; ++ks) {
                const int kg = (ks << 1) + hiA;
                uint32_t a0[4], a1[4];
                ldsm_x4(a0[0], a0[1], a0[2], a0[3],
                        abuf + aoff0 + (uint32_t)((kg ^ xa0) << 4));
                ldsm_x4(a1[0], a1[1], a1[2], a1[3],
                        abuf + aoff1 + (uint32_t)((kg ^ xa1) << 4));

                const int ga = (sub << 2) + (ks << 1) + gsel;
#pragma unroll
                for (int ntp = 0; ntp < 4; ++ntp) {
                    int slot = sbl + (ntp << 4) + dxp;
                    uint32_t addr = rowbase + (uint32_t)(slot << 7)
                                  + (uint32_t)((ga ^ (slot & 7)) << 4);
                    uint32_t b0, b1, b2, b3;
                    ldsm_x4(b0, b1, b2, b3, addr);

                    const int nt0 = ntp << 1;
#pragma unroll
                    for (int half = 0; half < 2; ++half) {
                        uint32_t bb0 = half ? b2 : b0;
                        uint32_t bb1 = half ? b3 : b1;
                        int nt = nt0 + half;
                        asm volatile(
                            "mma.sync.aligned.m16n8k16.row.col.f32.f16.f16.f32 "
                            "{%0,%1,%2,%3}, {%4,%5,%6,%7}, {%8,%9}, {%0,%1,%2,%3};"
                            : "+f"(acc[0][nt][0]), "+f"(acc[0][nt][1]),
                              "+f"(acc[0][nt][2]), "+f"(acc[0][nt][3])
                            : "r"(a0[0]), "r"(a0[1]), "r"(a0[2]), "r"(a0[3]),
                              "r"(bb0), "r"(bb1));
                        asm volatile(
                            "mma.sync.aligned.m16n8k16.row.col.f32.f16.f16.f32 "
                            "{%0,%1,%2,%3}, {%4,%5,%6,%7}, {%8,%9}, {%0,%1,%2,%3};"
                            : "+f"(acc[1][nt][0]), "+f"(acc[1][nt][1]),
                              "+f"(acc[1][nt][2]), "+f"(acc[1][nt][3])
                            : "r"(a1[0]), "r"(a1[1]), "r"(a1[2]), "r"(a1[3]),
                              "r"(bb0), "r"(bb1));
                    }
                }
            }
        }
        issueA(ktp + 4);
        issueA(ktp + 5);
    }

    // ---- epilogue: bias; all sets -> fp16 planes (sigmoid for sets 0/2) ----
    const int set = m0 >> 8;
    const int chb = m0 & 255;
#pragma unroll
    for (int mt = 0; mt < 2; ++mt) {
#pragma unroll
        for (int rr = 0; rr < 2; ++rr) {
            int cloc = (wm << 5) + (mt << 4) + (l >> 2) + (rr << 3);
            float bias = gBias[m0 + cloc];
            int ch = chb + cloc;
            size_t base = (((size_t)b * C4 + ch) << 16) + ((size_t)y0 << 8) + x0;
#pragma unroll
            for (int nt = 0; nt < 8; ++nt) {
                int n = (wn << 6) + (nt << 3) + ((l & 3) << 1);
                float v0 = acc[mt][nt][rr * 2 + 0] + bias;
                float v1 = acc[mt][nt][rr * 2 + 1] + bias;
                if (set == 1) {
                    *(__half2*)&gH[base + n] = __floats2half2_rn(v0, v1);
                } else {
                    __half2 h2 = __floats2half2_rn(fast_sigmoid(v0),
                                                   fast_sigmoid(v1));
                    if (set == 0) *(__half2*)&gZ[base + n] = h2;
                    else          *(__half2*)&gS[base + n] = h2;
                }
            }
        }
    }
}

// ---------------------------------------------------------------------------
// Vertical scan phase A: per-segment affine composition (A,B) over 32 rows.
// ---------------------------------------------------------------------------
__global__ __launch_bounds__(256)
void segscan_v_kernel()
{
    const int x   = threadIdx.x;
    const int blk = blockIdx.x;
    const int seg = blk & 7;
    const int c   = (blk >> 3) & 63;
    const int b   = (blk >> 9) & 3;
    const int g   = blk >> 11;

    const size_t pb = (((size_t)b * C4 + g * 64 + c) << 16) + x;

    float A = 1.f, Bv = 0.f;
    const int ybase = seg << 5;
    if (g == 0) {
#pragma unroll 8
        for (int i = 0; i < 32; ++i) {
            size_t off = (size_t)(ybase + i) << 8;
            float z  = __half2float(gZ[pb + off]);
            float hv = __half2float(gH[pb + off]);
            float ai = 1.f - z;
            Bv = fmaf(ai, Bv, z * hv);
            A  = A * ai;
        }
    } else {
#pragma unroll 8
        for (int i = 31; i >= 0; --i) {
            size_t off = (size_t)(ybase + i) << 8;
            float z  = __half2float(gZ[pb + off]);
            float hv = __half2float(gH[pb + off]);
            float ai = 1.f - z;
            Bv = fmaf(ai, Bv, z * hv);
            A  = A * ai;
        }
    }
    gSeg[(size_t)blk * 256 + x] = make_float2(A, Bv);
}

// ---------------------------------------------------------------------------
// Fused tail: vertical apply (groups 0,1) into smem, then horizontal scans
// (groups 2,3) per row, single write of out.
// ---------------------------------------------------------------------------
__global__ __launch_bounds__(256)
void scan_tail_kernel(const float* __restrict__ h20,
                      const float* __restrict__ h21,
                      const float* __restrict__ h30,
                      const float* __restrict__ h31,
                      float* __restrict__ out)
{
    __shared__ float Sbuf[256][33];

    const int blk = blockIdx.x;
    const int seg = blk & 7;
    const int c   = (blk >> 3) & 63;
    const int b   = blk >> 9;
    const int tid = threadIdx.x;
    const int warp = tid >> 5;
    const int lane = tid & 31;

    // ================= part 1: vertical apply for column x = tid ===========
    {
        const int x = tid;
        float st0 = h20[c];
        {
            const size_t base = ((size_t)((0 * 4 + b) * 64 + c) * 8) * 256 + x;
            for (int k = 0; k < seg; ++k) {
                float2 f = gSeg[base + (size_t)k * 256];
                st0 = fmaf(f.x, st0, f.y);
            }
        }
        float st1 = h21[c];
        {
            const size_t base = ((size_t)((1 * 4 + b) * 64 + c) * 8) * 256 + x;
            for (int k = 7; k > seg; --k) {
                float2 f = gSeg[base + (size_t)k * 256];
                st1 = fmaf(f.x, st1, f.y);
            }
        }

        const int ybase = seg << 5;
        const size_t p0 = (((size_t)b * C4 + c) << 16) + x;
        const size_t p1 = p0 + ((size_t)64 << 16);

#pragma unroll
        for (int i = 0; i < 32; ++i) {
            size_t off = (size_t)(ybase + i) << 8;
            float z  = __half2float(gZ[p0 + off]);
            float hv = __half2float(gH[p0 + off]);
            float s  = __half2float(gS[p0 + off]);
            st0 = z * hv + (1.f - z) * st0;
            Sbuf[x][i] = s * st0;
        }
#pragma unroll
        for (int i = 31; i >= 0; --i) {
            size_t off = (size_t)(ybase + i) << 8;
            float z  = __half2float(gZ[p1 + off]);
            float hv = __half2float(gH[p1 + off]);
            float s  = __half2float(gS[p1 + off]);
            st1 = z * hv + (1.f - z) * st1;
            Sbuf[x][i] += s * st1;
        }
    }
    __syncthreads();

    // ================= part 2: horizontal scans ============================
    const float hi30 = h30[c];
    const float hi31 = h31[c];
    const size_t p2 = ((size_t)b * C4 + 128 + c) << 16;
    const size_t p3 = ((size_t)b * C4 + 192 + c) << 16;
    const size_t ob = ((size_t)b * 64 + c) << 16;

    for (int rr = 0; rr < 4; ++rr) {
        const int rloc = warp * 4 + rr;
        const int y = (seg << 5) + rloc;
        const size_t ro = ((size_t)y << 8) + lane * 8;

        float res[8];

        // ---- group 2: forward scan ----
        {
            float zz[8], qq[8], ss[8];
            ld8h(&gZ[p2 + ro], zz);
            ld8h(&gH[p2 + ro], qq);
            float A[8], Bv[8];
            float ra = 1.f, rb = 0.f;
#pragma unroll
            for (int i = 0; i < 8; ++i) {
                float ai = 1.f - zz[i];
                float bi = zz[i] * qq[i];
                rb = fmaf(ai, rb, bi);
                ra = ra * ai;
                A[i] = ra; Bv[i] = rb;
            }
            float ga = ra, gb = rb;
#pragma unroll
            for (int off = 1; off < 32; off <<= 1) {
                float pa = __shfl_up_sync(0xFFFFFFFFu, ga, off);
                float pb = __shfl_up_sync(0xFFFFFFFFu, gb, off);
                if (lane >= off) { gb = fmaf(ga, pb, gb); ga = ga * pa; }
            }
            float PA = __shfl_up_sync(0xFFFFFFFFu, ga, 1);
            float PB = __shfl_up_sync(0xFFFFFFFFu, gb, 1);
            if (lane == 0) { PA = 1.f; PB = 0.f; }
            float base = fmaf(PA, hi30, PB);
            ld8h(&gS[p2 + ro], ss);
#pragma unroll
            for (int i = 0; i < 8; ++i)
                res[i] = ss[i] * fmaf(A[i], base, Bv[i]);
        }

        // ---- group 3: reverse scan ----
        {
            float zz[8], qq[8], ss[8];
            ld8h(&gZ[p3 + ro], zz);
            ld8h(&gH[p3 + ro], qq);
            float A[8], Bv[8];
            float ra = 1.f, rb = 0.f;
#pragma unroll
            for (int i = 7; i >= 0; --i) {
                float ai = 1.f - zz[i];
                float bi = zz[i] * qq[i];
                rb = fmaf(ai, rb, bi);
                ra = ra * ai;
                A[i] = ra; Bv[i] = rb;
            }
            float ga = ra, gb = rb;
#pragma unroll
            for (int off = 1; off < 32; off <<= 1) {
                float pa = __shfl_down_sync(0xFFFFFFFFu, ga, off);
                float pb = __shfl_down_sync(0xFFFFFFFFu, gb, off);
                if (lane + off < 32) { gb = fmaf(ga, pb, gb); ga = ga * pa; }
            }
            float PA = __shfl_down_sync(0xFFFFFFFFu, ga, 1);
            float PB = __shfl_down_sync(0xFFFFFFFFu, gb, 1);
            if (lane == 31) { PA = 1.f; PB = 0.f; }
            float base = fmaf(PA, hi31, PB);
            ld8h(&gS[p3 + ro], ss);
#pragma unroll
            for (int i = 0; i < 8; ++i)
                res[i] += ss[i] * fmaf(A[i], base, Bv[i]);
        }

        float4 olo, ohi;
        olo.x = res[0] + Sbuf[lane * 8 + 0][rloc];
        olo.y = res[1] + Sbuf[lane * 8 + 1][rloc];
        olo.z = res[2] + Sbuf[lane * 8 + 2][rloc];
        olo.w = res[3] + Sbuf[lane * 8 + 3][rloc];
        ohi.x = res[4] + Sbuf[lane * 8 + 4][rloc];
        ohi.y = res[5] + Sbuf[lane * 8 + 5][rloc];
        ohi.z = res[6] + Sbuf[lane * 8 + 6][rloc];
        ohi.w = res[7] + Sbuf[lane * 8 + 7][rloc];
        *(float4*)&out[ob + ro]     = olo;
        *(float4*)&out[ob + ro + 4] = ohi;
    }
}

// ---------------------------------------------------------------------------
extern "C" void kernel_launch(void* const* d_in, const int* in_sizes, int n_in,
                              void* d_out, int out_size)
{
    const float* xs = (const float*)d_in[0];

    ConvParams P;
    for (int s = 0; s < 3; ++s) {
        int base = 1 + s * 5;
        P.w[s] = (const float*)d_in[base + 0];
        P.g[s] = (const float*)d_in[base + 1];
        P.b[s] = (const float*)d_in[base + 2];
        P.m[s] = (const float*)d_in[base + 3];
        P.v[s] = (const float*)d_in[base + 4];
    }
    const float* h20 = (const float*)d_in[16];
    const float* h21 = (const float*)d_in[17];
    const float* h30 = (const float*)d_in[18];
    const float* h31 = (const float*)d_in[19];

    float* out = (float*)d_out;

    cudaFuncSetAttribute(conv_mma_kernel,
                         cudaFuncAttributeMaxDynamicSharedMemorySize, SMEM_BYTES);

    prep_fused_kernel<<<2048 + 1728, 256>>>(xs, P);

    dim3 cgrid(512, 6, 4);
    conv_mma_kernel<<<cgrid, 256, SMEM_BYTES>>>();

    segscan_v_kernel<<<4096, 256>>>();
    scan_tail_kernel<<<2048, 256>>>(h20, h21, h30, h31, out);
}

// round 15
// speedup vs baseline: 1.1465x; 1.0000x over previous
#include <cuda_runtime.h>
#include <cuda_fp16.h>
#include <math.h>
#include <stdint.h>

// ---------------------------------------------------------------------------
// MiniGRUConv2d4 on GB300 (compute_103 PTX target -> legacy mma.sync path):
//   pass 1: fused (transpose xs -> xh fp16) + (fold BN into fp16 weights)
//   pass 2: 3x(conv3x3+BN[+sigmoid]) implicit GEMM, fp16 mma.sync.m16n8k16,
//           6-deep A ring, ONE syncthreads per 2 k-steps (race-free write
//           set: buffers {kt+4,kt+5}%6 disjoint from current/next reads).
//   pass 3: vertical scans: segment compose + fused apply/horizontal tail.
// ---------------------------------------------------------------------------

#define B_  4
#define CIN 64
#define C4  256

static __device__ __half gH[(size_t)B_ * C4 * 256 * 256];            // h plane
static __device__ __half gZ[(size_t)B_ * C4 * 256 * 256];            // z plane
static __device__ __half gS[(size_t)B_ * C4 * 256 * 256];            // s plane
static __device__ __align__(16) __half gXh[(size_t)B_ * 256 * 256 * 64];
static __device__ __align__(16) __half gWtH[768 * 576];
static __device__ float gBias[768];
static __device__ float2 gSeg[2 * 4 * 64 * 8 * 256];                 // seg (A,B)

struct ConvParams {
    const float* w[3];
    const float* g[3];
    const float* b[3];
    const float* m[3];
    const float* v[3];
};

// ---------------- fast sigmoid (no MUFU) ------------------------------------
__device__ __forceinline__ float fast_sigmoid(float x)
{
    float u = -1.44269504f * x;
    u = fminf(fmaxf(u, -60.f), 60.f);
    float fi = rintf(u);
    float f  = u - fi;
    float p = 1.54035304e-4f;
    p = fmaf(p, f, 1.33335581e-3f);
    p = fmaf(p, f, 9.61812910e-3f);
    p = fmaf(p, f, 5.55041087e-2f);
    p = fmaf(p, f, 2.40226507e-1f);
    p = fmaf(p, f, 6.93147181e-1f);
    p = fmaf(p, f, 1.0f);
    int ei = (int)fi;
    float e = __int_as_float(__float_as_int(p) + (ei << 23));
    float d = 1.0f + e;
    float r = __int_as_float(0x7EF311C3 - __float_as_int(d));
    r = r * (2.0f - d * r);
    r = r * (2.0f - d * r);
    r = r * (2.0f - d * r);
    return r;
}

// ---------------- small helpers ---------------------------------------------
__device__ __forceinline__ uint32_t smem_u32(const void* p)
{
    uint32_t a;
    asm("{ .reg .u64 t; cvta.to.shared.u64 t, %1; cvt.u32.u64 %0, t; }"
        : "=r"(a) : "l"(p));
    return a;
}
__device__ __forceinline__ void cp16(uint32_t dst, const void* src)
{
    size_t g = __cvta_generic_to_global(src);
    asm volatile("cp.async.cg.shared.global [%0], [%1], 16;"
                 :: "r"(dst), "l"(g) : "memory");
}
__device__ __forceinline__ void sts_zero16(uint32_t a)
{
    asm volatile("st.shared.v4.u32 [%0], {%1,%1,%1,%1};" :: "r"(a), "r"(0u) : "memory");
}
__device__ __forceinline__ void ldsm_x4(uint32_t& r0, uint32_t& r1,
                                        uint32_t& r2, uint32_t& r3, uint32_t a)
{
    asm volatile("ldmatrix.sync.aligned.m8n8.x4.shared.b16 {%0,%1,%2,%3}, [%4];"
                 : "=r"(r0), "=r"(r1), "=r"(r2), "=r"(r3) : "r"(a));
}
// load 8 consecutive halves -> 8 floats
__device__ __forceinline__ void ld8h(const __half* p, float* d)
{
    uint4 u = *(const uint4*)p;
    const __half2* h = (const __half2*)&u;
    float2 f0 = __half22float2(h[0]);
    float2 f1 = __half22float2(h[1]);
    float2 f2 = __half22float2(h[2]);
    float2 f3 = __half22float2(h[3]);
    d[0] = f0.x; d[1] = f0.y; d[2] = f1.x; d[3] = f1.y;
    d[4] = f2.x; d[5] = f2.y; d[6] = f3.x; d[7] = f3.y;
}

// ---------------------------------------------------------------------------
// Fused prep: blocks [0,2048) transpose xs -> gXh; blocks [2048,3776) fold BN
// weights -> gWtH (+ bias).
// ---------------------------------------------------------------------------
__global__ __launch_bounds__(256)
void prep_fused_kernel(const float* __restrict__ xs, ConvParams P)
{
    const int blk = blockIdx.x;
    const int tid = threadIdx.x;

    if (blk >= 2048) {
        int idx = (blk - 2048) * 256 + tid;
        if (idx < 768) {
            int set = idx >> 8, co = idx & 255;
            float inv = P.g[set][co] * rsqrtf(P.v[set][co] + 1e-5f);
            gBias[idx] = P.b[set][co] - P.m[set][co] * inv;
        }
        if (idx < 768 * 576) {
            int co_g = idx / 576;
            int k    = idx - co_g * 576;
            int r    = k >> 6;
            int ci   = k & 63;
            int set  = co_g >> 8;
            int co   = co_g & 255;
            float inv = P.g[set][co] * rsqrtf(P.v[set][co] + 1e-5f);
            gWtH[idx] = __float2half_rn(P.w[set][(co * 64 + ci) * 9 + r] * inv);
        }
        return;
    }

    __shared__ float S[64][129];
    const int xt = blk & 1;
    const int y  = (blk >> 1) & 255;
    const int b  = blk >> 9;

    const float* src = xs + (((size_t)b * CIN) << 16) + (y << 8) + xt * 128;
#pragma unroll
    for (int p = 0; p < 8; ++p) {
        int idx = tid + (p << 8);
        int ci  = idx >> 5;
        int x4  = idx & 31;
        float4 v = *(const float4*)(src + (((size_t)ci) << 16) + (x4 << 2));
        S[ci][x4 * 4 + 0] = v.x;
        S[ci][x4 * 4 + 1] = v.y;
        S[ci][x4 * 4 + 2] = v.z;
        S[ci][x4 * 4 + 3] = v.w;
    }
    __syncthreads();

    __half* dst = gXh + ((((size_t)b * 256 + y) * 256) + xt * 128) * 64;
#pragma unroll
    for (int p = 0; p < 4; ++p) {
        int chunk = tid + (p << 8);
        int g = chunk & 7;
        int x = chunk >> 3;
        int c0 = g * 8;
        __half2 h0 = __floats2half2_rn(S[c0 + 0][x], S[c0 + 1][x]);
        __half2 h1 = __floats2half2_rn(S[c0 + 2][x], S[c0 + 3][x]);
        __half2 h2 = __floats2half2_rn(S[c0 + 4][x], S[c0 + 5][x]);
        __half2 h3 = __floats2half2_rn(S[c0 + 6][x], S[c0 + 7][x]);
        uint4 val;
        val.x = *(uint32_t*)&h0; val.y = *(uint32_t*)&h1;
        val.z = *(uint32_t*)&h2; val.w = *(uint32_t*)&h3;
        *(uint4*)(dst + (size_t)x * 64 + g * 8) = val;
    }
}

// ---------------------------------------------------------------------------
// Conv: CTA = 128 px x 128 couts, 8 warps (4m x 2n), warp 32co x 64px.
// ldmatrix fragment loads; 6-deep A ring; 1 sync per 2 kt; 2 CTAs/SM.
// ---------------------------------------------------------------------------
#define BT_STRIDE 132
#define BT_BYTES  (3 * BT_STRIDE * 128)          // 50688
#define A_BUF     8192
#define SMEM_BYTES (BT_BYTES + 6 * A_BUF)        // 99840

__global__ __launch_bounds__(256, 2)
void conv_mma_kernel()
{
    extern __shared__ char smem[];
    const uint32_t sB = smem_u32(smem);
    const uint32_t sA = sB + BT_BYTES;

    const int tid = threadIdx.x;
    const int l   = tid & 31;
    const int w   = tid >> 5;
    const int wm  = w >> 1;            // 0..3 (32 co each)
    const int wn  = w & 1;             // 0..1 (64 px each)

    const int bx = blockIdx.x;         // 0..511
    const int y0 = bx >> 1;
    const int x0 = (bx & 1) << 7;
    const int m0 = blockIdx.y << 7;    // 0..640
    const int b  = blockIdx.z;

    // ---- A ring producer: 128co x 32k fp16 per chunk; buffer = s % 6 ----
    auto issueA = [&](int s) {
        if (s < 18) {
            uint32_t base = sA + (uint32_t)((s % 6) * A_BUF);
            const __half* src = gWtH + (size_t)m0 * 576 + s * 32;
#pragma unroll
            for (int p = 0; p < 2; ++p) {
                int chunk = tid + (p << 8);
                int co  = chunk >> 2;
                int kpg = chunk & 3;
                uint32_t wrd = (uint32_t)(co << 4)
                             + (uint32_t)((kpg ^ ((co >> 1) & 3)) << 2);
                cp16(base + (wrd << 2), src + (size_t)co * 576 + (kpg << 3));
            }
        }
        asm volatile("cp.async.commit_group;" ::: "memory");
    };

    // ---- progressive B halo fill: row r goes in cp.async group r ----
    for (int row = 0; row < 3; ++row) {
        const int y = y0 - 1 + row;
        const bool rok = (unsigned)y < 256u;
        for (int t = tid; t < 1040; t += 256) {
            int slot = t >> 3;
            int g    = t & 7;
            int x    = x0 + slot - 1;
            uint32_t dst = sB + (uint32_t)(row * BT_STRIDE + slot) * 128
                         + (uint32_t)((g ^ (slot & 7)) << 4);
            if (rok && (unsigned)x < 256u)
                cp16(dst, gXh + ((((size_t)b * 256 + y) * 256 + x) * 64 + g * 8));
            else
                sts_zero16(dst);
        }
        issueA(row);
    }
    issueA(3);

    // ---- per-lane ldmatrix address constants ----
    const int hiA   = l >> 4;
    const int cA0   = (wm << 5) + (l & 15);
    const int cA1   = cA0 + 16;
    const int xa0   = (cA0 >> 1) & 3;
    const int xa1   = (cA1 >> 1) & 3;
    const uint32_t aoff0 = (uint32_t)(cA0 << 6);
    const uint32_t aoff1 = (uint32_t)(cA1 << 6);
    const int gsel  = (l >> 3) & 1;
    const int sbl   = (wn << 6) + (l & 7) + ((l >> 4) << 3);

    float acc[2][8][4];
#pragma unroll
    for (int mt = 0; mt < 2; ++mt)
#pragma unroll
        for (int nt = 0; nt < 8; ++nt)
#pragma unroll
            for (int c = 0; c < 4; ++c) acc[mt][nt][c] = 0.f;

    for (int ktp = 0; ktp < 18; ktp += 2) {
        asm volatile("cp.async.wait_group 2;" ::: "memory");
        __syncthreads();

        // kt pair shares r (= ktp>>1), hence same halo row and dx shift
        const int r   = ktp >> 1;
        const int row = r / 3;
        const int dxp = r - row * 3;
        const uint32_t rowbase = sB + (uint32_t)(row * BT_STRIDE) * 128;

#pragma unroll
        for (int sub = 0; sub < 2; ++sub) {
            const int kt = ktp + sub;
            const uint32_t abuf = sA + (uint32_t)((kt % 6) * A_BUF);

#pragma unroll
            for (int ks = 0; ks < 2; ++ks) {
                const int kg = (ks << 1) + hiA;
                uint32_t a0[4], a1[4];
                ldsm_x4(a0[0], a0[1], a0[2], a0[3],
                        abuf + aoff0 + (uint32_t)((kg ^ xa0) << 4));
                ldsm_x4(a1[0], a1[1], a1[2], a1[3],
                        abuf + aoff1 + (uint32_t)((kg ^ xa1) << 4));

                const int ga = (sub << 2) + (ks << 1) + gsel;
#pragma unroll
                for (int ntp = 0; ntp < 4; ++ntp) {
                    int slot = sbl + (ntp << 4) + dxp;
                    uint32_t addr = rowbase + (uint32_t)(slot << 7)
                                  + (uint32_t)((ga ^ (slot & 7)) << 4);
                    uint32_t b0, b1, b2, b3;
                    ldsm_x4(b0, b1, b2, b3, addr);

                    const int nt0 = ntp << 1;
#pragma unroll
                    for (int half = 0; half < 2; ++half) {
                        uint32_t bb0 = half ? b2 : b0;
                        uint32_t bb1 = half ? b3 : b1;
                        int nt = nt0 + half;
                        asm volatile(
                            "mma.sync.aligned.m16n8k16.row.col.f32.f16.f16.f32 "
                            "{%0,%1,%2,%3}, {%4,%5,%6,%7}, {%8,%9}, {%0,%1,%2,%3};"
                            : "+f"(acc[0][nt][0]), "+f"(acc[0][nt][1]),
                              "+f"(acc[0][nt][2]), "+f"(acc[0][nt][3])
                            : "r"(a0[0]), "r"(a0[1]), "r"(a0[2]), "r"(a0[3]),
                              "r"(bb0), "r"(bb1));
                        asm volatile(
                            "mma.sync.aligned.m16n8k16.row.col.f32.f16.f16.f32 "
                            "{%0,%1,%2,%3}, {%4,%5,%6,%7}, {%8,%9}, {%0,%1,%2,%3};"
                            : "+f"(acc[1][nt][0]), "+f"(acc[1][nt][1]),
                              "+f"(acc[1][nt][2]), "+f"(acc[1][nt][3])
                            : "r"(a1[0]), "r"(a1[1]), "r"(a1[2]), "r"(a1[3]),
                              "r"(bb0), "r"(bb1));
                    }
                }
            }
        }
        issueA(ktp + 4);
        issueA(ktp + 5);
    }

    // ---- epilogue: bias; all sets -> fp16 planes (sigmoid for sets 0/2) ----
    const int set = m0 >> 8;
    const int chb = m0 & 255;
#pragma unroll
    for (int mt = 0; mt < 2; ++mt) {
#pragma unroll
        for (int rr = 0; rr < 2; ++rr) {
            int cloc = (wm << 5) + (mt << 4) + (l >> 2) + (rr << 3);
            float bias = gBias[m0 + cloc];
            int ch = chb + cloc;
            size_t base = (((size_t)b * C4 + ch) << 16) + ((size_t)y0 << 8) + x0;
#pragma unroll
            for (int nt = 0; nt < 8; ++nt) {
                int n = (wn << 6) + (nt << 3) + ((l & 3) << 1);
                float v0 = acc[mt][nt][rr * 2 + 0] + bias;
                float v1 = acc[mt][nt][rr * 2 + 1] + bias;
                if (set == 1) {
                    *(__half2*)&gH[base + n] = __floats2half2_rn(v0, v1);
                } else {
                    __half2 h2 = __floats2half2_rn(fast_sigmoid(v0),
                                                   fast_sigmoid(v1));
                    if (set == 0) *(__half2*)&gZ[base + n] = h2;
                    else          *(__half2*)&gS[base + n] = h2;
                }
            }
        }
    }
}

// ---------------------------------------------------------------------------
// Vertical scan phase A: per-segment affine composition (A,B) over 32 rows.
// ---------------------------------------------------------------------------
__global__ __launch_bounds__(256)
void segscan_v_kernel()
{
    const int x   = threadIdx.x;
    const int blk = blockIdx.x;
    const int seg = blk & 7;
    const int c   = (blk >> 3) & 63;
    const int b   = (blk >> 9) & 3;
    const int g   = blk >> 11;

    const size_t pb = (((size_t)b * C4 + g * 64 + c) << 16) + x;

    float A = 1.f, Bv = 0.f;
    const int ybase = seg << 5;
    if (g == 0) {
#pragma unroll 8
        for (int i = 0; i < 32; ++i) {
            size_t off = (size_t)(ybase + i) << 8;
            float z  = __half2float(gZ[pb + off]);
            float hv = __half2float(gH[pb + off]);
            float ai = 1.f - z;
            Bv = fmaf(ai, Bv, z * hv);
            A  = A * ai;
        }
    } else {
#pragma unroll 8
        for (int i = 31; i >= 0; --i) {
            size_t off = (size_t)(ybase + i) << 8;
            float z  = __half2float(gZ[pb + off]);
            float hv = __half2float(gH[pb + off]);
            float ai = 1.f - z;
            Bv = fmaf(ai, Bv, z * hv);
            A  = A * ai;
        }
    }
    gSeg[(size_t)blk * 256 + x] = make_float2(A, Bv);
}

// ---------------------------------------------------------------------------
// Fused tail: vertical apply (groups 0,1) into smem, then horizontal scans
// (groups 2,3) per row, single write of out.
// ---------------------------------------------------------------------------
__global__ __launch_bounds__(256, 5)
void scan_tail_kernel(const float* __restrict__ h20,
                      const float* __restrict__ h21,
                      const float* __restrict__ h30,
                      const float* __restrict__ h31,
                      float* __restrict__ out)
{
    __shared__ float Sbuf[256][33];

    const int blk = blockIdx.x;
    const int seg = blk & 7;
    const int c   = (blk >> 3) & 63;
    const int b   = blk >> 9;
    const int tid = threadIdx.x;
    const int warp = tid >> 5;
    const int lane = tid & 31;

    // ================= part 1: vertical apply for column x = tid ===========
    {
        const int x = tid;
        float st0 = h20[c];
        {
            const size_t base = ((size_t)((0 * 4 + b) * 64 + c) * 8) * 256 + x;
            for (int k = 0; k < seg; ++k) {
                float2 f = gSeg[base + (size_t)k * 256];
                st0 = fmaf(f.x, st0, f.y);
            }
        }
        float st1 = h21[c];
        {
            const size_t base = ((size_t)((1 * 4 + b) * 64 + c) * 8) * 256 + x;
            for (int k = 7; k > seg; --k) {
                float2 f = gSeg[base + (size_t)k * 256];
                st1 = fmaf(f.x, st1, f.y);
            }
        }

        const int ybase = seg << 5;
        const size_t p0 = (((size_t)b * C4 + c) << 16) + x;
        const size_t p1 = p0 + ((size_t)64 << 16);

#pragma unroll
        for (int i = 0; i < 32; ++i) {
            size_t off = (size_t)(ybase + i) << 8;
            float z  = __half2float(gZ[p0 + off]);
            float hv = __half2float(gH[p0 + off]);
            float s  = __half2float(gS[p0 + off]);
            st0 = z * hv + (1.f - z) * st0;
            Sbuf[x][i] = s * st0;
        }
#pragma unroll
        for (int i = 31; i >= 0; --i) {
            size_t off = (size_t)(ybase + i) << 8;
            float z  = __half2float(gZ[p1 + off]);
            float hv = __half2float(gH[p1 + off]);
            float s  = __half2float(gS[p1 + off]);
            st1 = z * hv + (1.f - z) * st1;
            Sbuf[x][i] += s * st1;
        }
    }
    __syncthreads();

    // ================= part 2: horizontal scans ============================
    const float hi30 = h30[c];
    const float hi31 = h31[c];
    const size_t p2 = ((size_t)b * C4 + 128 + c) << 16;
    const size_t p3 = ((size_t)b * C4 + 192 + c) << 16;
    const size_t ob = ((size_t)b * 64 + c) << 16;

    for (int rr = 0; rr < 4; ++rr) {
        const int rloc = warp * 4 + rr;
        const int y = (seg << 5) + rloc;
        const size_t ro = ((size_t)y << 8) + lane * 8;

        float res[8];

        // ---- group 2: forward scan ----
        {
            float zz[8], qq[8], ss[8];
            ld8h(&gZ[p2 + ro], zz);
            ld8h(&gH[p2 + ro], qq);
            float A[8], Bv[8];
            float ra = 1.f, rb = 0.f;
#pragma unroll
            for (int i = 0; i < 8; ++i) {
                float ai = 1.f - zz[i];
                float bi = zz[i] * qq[i];
                rb = fmaf(ai, rb, bi);
                ra = ra * ai;
                A[i] = ra; Bv[i] = rb;
            }
            float ga = ra, gb = rb;
#pragma unroll
            for (int off = 1; off < 32; off <<= 1) {
                float pa = __shfl_up_sync(0xFFFFFFFFu, ga, off);
                float pb = __shfl_up_sync(0xFFFFFFFFu, gb, off);
                if (lane >= off) { gb = fmaf(ga, pb, gb); ga = ga * pa; }
            }
            float PA = __shfl_up_sync(0xFFFFFFFFu, ga, 1);
            float PB = __shfl_up_sync(0xFFFFFFFFu, gb, 1);
            if (lane == 0) { PA = 1.f; PB = 0.f; }
            float base = fmaf(PA, hi30, PB);
            ld8h(&gS[p2 + ro], ss);
#pragma unroll
            for (int i = 0; i < 8; ++i)
                res[i] = ss[i] * fmaf(A[i], base, Bv[i]);
        }

        // ---- group 3: reverse scan ----
        {
            float zz[8], qq[8], ss[8];
            ld8h(&gZ[p3 + ro], zz);
            ld8h(&gH[p3 + ro], qq);
            float A[8], Bv[8];
            float ra = 1.f, rb = 0.f;
#pragma unroll
            for (int i = 7; i >= 0; --i) {
                float ai = 1.f - zz[i];
                float bi = zz[i] * qq[i];
                rb = fmaf(ai, rb, bi);
                ra = ra * ai;
                A[i] = ra; Bv[i] = rb;
            }
            float ga = ra, gb = rb;
#pragma unroll
            for (int off = 1; off < 32; off <<= 1) {
                float pa = __shfl_down_sync(0xFFFFFFFFu, ga, off);
                float pb = __shfl_down_sync(0xFFFFFFFFu, gb, off);
                if (lane + off < 32) { gb = fmaf(ga, pb, gb); ga = ga * pa; }
            }
            float PA = __shfl_down_sync(0xFFFFFFFFu, ga, 1);
            float PB = __shfl_down_sync(0xFFFFFFFFu, gb, 1);
            if (lane == 31) { PA = 1.f; PB = 0.f; }
            float base = fmaf(PA, hi31, PB);
            ld8h(&gS[p3 + ro], ss);
#pragma unroll
            for (int i = 0; i < 8; ++i)
                res[i] += ss[i] * fmaf(A[i], base, Bv[i]);
        }

        float4 olo, ohi;
        olo.x = res[0] + Sbuf[lane * 8 + 0][rloc];
        olo.y = res[1] + Sbuf[lane * 8 + 1][rloc];
        olo.z = res[2] + Sbuf[lane * 8 + 2][rloc];
        olo.w = res[3] + Sbuf[lane * 8 + 3][rloc];
        ohi.x = res[4] + Sbuf[lane * 8 + 4][rloc];
        ohi.y = res[5] + Sbuf[lane * 8 + 5][rloc];
        ohi.z = res[6] + Sbuf[lane * 8 + 6][rloc];
        ohi.w = res[7] + Sbuf[lane * 8 + 7][rloc];
        *(float4*)&out[ob + ro]     = olo;
        *(float4*)&out[ob + ro + 4] = ohi;
    }
}

// ---------------------------------------------------------------------------
extern "C" void kernel_launch(void* const* d_in, const int* in_sizes, int n_in,
                              void* d_out, int out_size)
{
    const float* xs = (const float*)d_in[0];

    ConvParams P;
    for (int s = 0; s < 3; ++s) {
        int base = 1 + s * 5;
        P.w[s] = (const float*)d_in[base + 0];
        P.g[s] = (const float*)d_in[base + 1];
        P.b[s] = (const float*)d_in[base + 2];
        P.m[s] = (const float*)d_in[base + 3];
        P.v[s] = (const float*)d_in[base + 4];
    }
    const float* h20 = (const float*)d_in[16];
    const float* h21 = (const float*)d_in[17];
    const float* h30 = (const float*)d_in[18];
    const float* h31 = (const float*)d_in[19];

    float* out = (float*)d_out;

    cudaFuncSetAttribute(conv_mma_kernel,
                         cudaFuncAttributeMaxDynamicSharedMemorySize, SMEM_BYTES);

    prep_fused_kernel<<<2048 + 1728, 256>>>(xs, P);

    dim3 cgrid(512, 6, 4);
    conv_mma_kernel<<<cgrid, 256, SMEM_BYTES>>>();

    segscan_v_kernel<<<4096, 256>>>();
    scan_tail_kernel<<<2048, 256>>>(h20, h21, h30, h31, out);
}